// round 2
// baseline (speedup 1.0000x reference)
#include <cuda_runtime.h>
#include <cuda_bf16.h>

// ---------------------------------------------------------------------------
// Problem constants (fixed by the dataset)
// ---------------------------------------------------------------------------
#define MULC     32
#define ATTRC    16
#define RADIALC  8

// ---------------------------------------------------------------------------
// Device scratch (no allocations allowed -> __device__ globals)
// ---------------------------------------------------------------------------
__device__ __align__(16) float g_WE[4 * 8192];     // folded edge weights [b][(r*32+u)][w']
__device__ __align__(16) float g_WS[2 * 16384];    // folded node weights [s][(u*16+v)][w']
__device__ __align__(16) float g_M[10000 * 128];   // messages: [n][0..32)=Ms, [32..128)=Mv(u*3+i)

// ---------------------------------------------------------------------------
// Fold kernels.  c_edge = (1/sqrt8)*(1/8)*(1/sqrt32) = 1/128
//                c_node = (1/sqrt512)*(1/sqrt32)     = 1/128
// ---------------------------------------------------------------------------
__global__ void fold_edge_kernel(const float* __restrict__ Wgen,
                                 const float* __restrict__ L1s,
                                 const float* __restrict__ L1v)
{
    int idx = blockIdx.x * blockDim.x + threadIdx.x;   // < 32768
    int b   = idx >> 13;            // 0..3 (A,B,C,D)
    int rem = idx & 8191;
    int r   = rem >> 10;            // 0..7
    int u   = (rem >> 5) & 31;
    int wp  = rem & 31;

    const float* wg = Wgen + r * 4096 + b * 1024 + u * 32;
    const float* L  = (b == 1 || b == 2) ? L1v : L1s;   // B,C: vector path uses L1v

    float acc = 0.f;
#pragma unroll
    for (int w = 0; w < 32; w++) acc = fmaf(wg[w], L[w * 32 + wp], acc);

    float c = 0.0078125f;                    // 1/128
    if (b == 3) c *= 0.57735026918962576f;   // WD also folds 1/sqrt(3) of the dot
    g_WE[b * 8192 + (r * 32 + u) * 32 + wp] = acc * c;
}

__global__ void fold_node_kernel(const float* __restrict__ WS0,
                                 const float* __restrict__ WS1,
                                 const float* __restrict__ L2s,
                                 const float* __restrict__ L2v)
{
    int idx = blockIdx.x * blockDim.x + threadIdx.x;   // < 32768
    int sb  = idx >> 14;            // 0: scalar (WS0/L2s), 1: vector (WS1/L2v)
    int rem = idx & 16383;
    int uv  = rem >> 5;             // u*16+v
    int wp  = rem & 31;

    const float* ws = (sb ? WS1 : WS0) + uv * 32;
    const float* L  = sb ? L2v : L2s;

    float acc = 0.f;
#pragma unroll
    for (int w = 0; w < 32; w++) acc = fmaf(ws[w], L[w * 32 + wp], acc);

    g_WS[sb * 16384 + uv * 32 + wp] = acc * 0.0078125f;
}

__global__ void zero_m_kernel(int n)
{
    int i = blockIdx.x * blockDim.x + threadIdx.x;
    if (i < n) g_M[i] = 0.f;
}

// ---------------------------------------------------------------------------
// Edge kernel: 512 threads, persistent grid, 64-edge tiles.
// smem float offsets:
// ---------------------------------------------------------------------------
#define EW_OFF   0          // 4*8192 folded weights
#define EXS_OFF  32768      // [32][65]
#define EXV_OFF(i) (34848 + (i) * 2080)   // 3 x [32][65]
#define EDOT_OFF 41088      // [32][65]
#define EEF_OFF  43168      // [8][64]
#define EYS_OFF  43680      // [64]
#define EYV_OFF  43744      // [3][64]
#define EA0_OFF  43936      // [32][64]
#define EA1_OFF(i) (45984 + (i) * 2048)   // 3 x [32][64]
#define EA2_OFF  52128      // [32][64]
#define ESND_OFF 54176      // int[64]
#define ERCV_OFF 54240      // int[64]
#define EDGE_SMEM_FLOATS 54304
#define EDGE_SMEM_BYTES  (EDGE_SMEM_FLOATS * 4)

__global__ void __launch_bounds__(512, 1)
edge_kernel(const float* __restrict__ node_feats,
            const float* __restrict__ edge_attrs,
            const float* __restrict__ edge_feats,
            const int*   __restrict__ edge_index,
            int E)
{
    extern __shared__ float s[];
    const int tid  = threadIdx.x;
    const int lane = tid & 31;
    const int eo   = tid >> 5;     // warp 0..15
    const int eb   = eo << 2;      // this warp's 4 edges within tile

    // stage folded weights once per block (128 KB)
    for (int i = tid; i < 8192; i += 512)
        ((float4*)s)[i] = ((const float4*)g_WE)[i];

    int* sSnd = (int*)&s[ESND_OFF];
    int* sRcv = (int*)&s[ERCV_OFF];

    const int ntiles = (E + 63) >> 6;

    for (int t = blockIdx.x; t < ntiles; t += gridDim.x) {
        const int e0 = t << 6;
        __syncthreads();   // protect smem reuse across tiles (covers weight load on 1st)

        // ---- indices + edge_attrs (64 threads) ----
        if (tid < 64) {
            int ge = e0 + tid;
            if (ge < E) {
                sSnd[tid] = edge_index[ge];
                sRcv[tid] = edge_index[E + ge];
                float4 ea = *(const float4*)&edge_attrs[(size_t)ge * 4];
                s[EYS_OFF + tid]       = ea.x;
                s[EYV_OFF + tid]       = ea.y;
                s[EYV_OFF + 64 + tid]  = ea.z;
                s[EYV_OFF + 128 + tid] = ea.w;
            } else {
                sSnd[tid] = 0; sRcv[tid] = -1;
                s[EYS_OFF + tid] = 0.f;
                s[EYV_OFF + tid] = 0.f; s[EYV_OFF + 64 + tid] = 0.f; s[EYV_OFF + 128 + tid] = 0.f;
            }
        }
        // ---- radial features ef[r][e] (all 512 threads) ----
        {
            int e = tid >> 3, r = tid & 7;
            int ge = e0 + e;
            s[EEF_OFF + r * 64 + e] = (ge < E) ? edge_feats[(size_t)ge * 8 + r] : 0.f;
        }
        __syncthreads();

        // ---- gather sender features ----
        for (int q = tid; q < 64 * 128; q += 512) {
            int e = q >> 7, f = q & 127;
            float v = node_feats[(size_t)sSnd[e] * 128 + f];
            if (f < 32) {
                s[EXS_OFF + f * 65 + e] = v;
            } else {
                int tt = f - 32;
                int uu = tt / 3;
                int ii = tt - uu * 3;
                s[EXV_OFF(ii) + uu * 65 + e] = v;
            }
        }
        __syncthreads();

        // ---- dot[u][e] = xv . yv  (1/sqrt3 is folded into WD) ----
        for (int q = tid; q < 2048; q += 512) {
            int u = q >> 6, e = q & 63;
            float d = s[EXV_OFF(0) + u * 65 + e] * s[EYV_OFF + e]
                    + s[EXV_OFF(1) + u * 65 + e] * s[EYV_OFF + 64 + e]
                    + s[EXV_OFF(2) + u * 65 + e] * s[EYV_OFF + 128 + e];
            s[EDOT_OFF + u * 65 + e] = d;
        }

        float accA[4] = {0,0,0,0}, accB[4] = {0,0,0,0}, accD[4] = {0,0,0,0};
        float accC[3][4] = {{0,0,0,0},{0,0,0,0},{0,0,0,0}};

        // ---- main contraction, chunked over r ----
        for (int r = 0; r < 8; r++) {
            __syncthreads();
            // build a-chunk for this r
            for (int q = tid; q < 2048; q += 512) {
                int u = q >> 6, e = q & 63;
                float efv = s[EEF_OFF + r * 64 + e];
                s[EA0_OFF    + q] = efv * s[EXS_OFF    + u * 65 + e];
                s[EA1_OFF(0) + q] = efv * s[EXV_OFF(0) + u * 65 + e];
                s[EA1_OFF(1) + q] = efv * s[EXV_OFF(1) + u * 65 + e];
                s[EA1_OFF(2) + q] = efv * s[EXV_OFF(2) + u * 65 + e];
                s[EA2_OFF    + q] = efv * s[EDOT_OFF   + u * 65 + e];
            }
            __syncthreads();

            const int kbase = (r << 5);
#pragma unroll 8
            for (int u = 0; u < 32; u++) {
                int ko = (kbase + u) * 32 + lane;
                float wa = s[EW_OFF         + ko];
                float wb = s[EW_OFF +  8192 + ko];
                float wc = s[EW_OFF + 16384 + ko];
                float wd = s[EW_OFF + 24576 + ko];
                int ao = (u << 6) + eb;
                float4 a0  = *(const float4*)&s[EA0_OFF    + ao];
                float4 a10 = *(const float4*)&s[EA1_OFF(0) + ao];
                float4 a11 = *(const float4*)&s[EA1_OFF(1) + ao];
                float4 a12 = *(const float4*)&s[EA1_OFF(2) + ao];
                float4 a2  = *(const float4*)&s[EA2_OFF    + ao];

                accA[0] = fmaf(a0.x, wa, accA[0]); accA[1] = fmaf(a0.y, wa, accA[1]);
                accA[2] = fmaf(a0.z, wa, accA[2]); accA[3] = fmaf(a0.w, wa, accA[3]);
                accB[0] = fmaf(a0.x, wb, accB[0]); accB[1] = fmaf(a0.y, wb, accB[1]);
                accB[2] = fmaf(a0.z, wb, accB[2]); accB[3] = fmaf(a0.w, wb, accB[3]);
                accC[0][0] = fmaf(a10.x, wc, accC[0][0]); accC[0][1] = fmaf(a10.y, wc, accC[0][1]);
                accC[0][2] = fmaf(a10.z, wc, accC[0][2]); accC[0][3] = fmaf(a10.w, wc, accC[0][3]);
                accC[1][0] = fmaf(a11.x, wc, accC[1][0]); accC[1][1] = fmaf(a11.y, wc, accC[1][1]);
                accC[1][2] = fmaf(a11.z, wc, accC[1][2]); accC[1][3] = fmaf(a11.w, wc, accC[1][3]);
                accC[2][0] = fmaf(a12.x, wc, accC[2][0]); accC[2][1] = fmaf(a12.y, wc, accC[2][1]);
                accC[2][2] = fmaf(a12.z, wc, accC[2][2]); accC[2][3] = fmaf(a12.w, wc, accC[2][3]);
                accD[0] = fmaf(a2.x, wd, accD[0]); accD[1] = fmaf(a2.y, wd, accD[1]);
                accD[2] = fmaf(a2.z, wd, accD[2]); accD[3] = fmaf(a2.w, wd, accD[3]);
            }
        }

        // ---- scatter-add into g_M[receiver] ----
#pragma unroll
        for (int j = 0; j < 4; j++) {
            int e = eb + j;
            int recv = sRcv[e];
            if (recv < 0) continue;
            float ysv = s[EYS_OFF + e];
            float yv0 = s[EYV_OFF + e], yv1 = s[EYV_OFF + 64 + e], yv2 = s[EYV_OFF + 128 + e];
            float* dst = g_M + (size_t)recv * 128;
            atomicAdd(dst + lane,                 fmaf(accA[j], ysv, accD[j]));
            atomicAdd(dst + 32 + lane * 3 + 0,    fmaf(accB[j], yv0, accC[0][j] * ysv));
            atomicAdd(dst + 32 + lane * 3 + 1,    fmaf(accB[j], yv1, accC[1][j] * ysv));
            atomicAdd(dst + 32 + lane * 3 + 2,    fmaf(accB[j], yv2, accC[2][j] * ysv));
        }
    }
}

// ---------------------------------------------------------------------------
// Node kernel: 512 threads, persistent grid, 64-node tiles.
// ---------------------------------------------------------------------------
#define NW_OFF   0          // 2*16384 folded weights
#define NMS_OFF  32768      // [32][65]
#define NMV_OFF(i) (34848 + (i) * 2080)
#define NNA_OFF  41088      // [16][65]
#define NA0_OFF  42128      // [16][64]
#define NA1_OFF(i) (43152 + (i) * 1024)
#define NODE_SMEM_FLOATS 46224
#define NODE_SMEM_BYTES  (NODE_SMEM_FLOATS * 4)

__global__ void __launch_bounds__(512, 1)
node_kernel(const float* __restrict__ node_attrs,
            float* __restrict__ out,
            int N)
{
    extern __shared__ float s[];
    const int tid  = threadIdx.x;
    const int lane = tid & 31;
    const int eo   = tid >> 5;
    const int eb   = eo << 2;

    for (int i = tid; i < 8192; i += 512)
        ((float4*)s)[i] = ((const float4*)g_WS)[i];

    const int ntiles = (N + 63) >> 6;

    for (int t = blockIdx.x; t < ntiles; t += gridDim.x) {
        const int n0 = t << 6;
        __syncthreads();

        // ---- stage Ms / Mv ----
        for (int q = tid; q < 64 * 128; q += 512) {
            int e = q >> 7, f = q & 127;
            int n = n0 + e;
            float v = (n < N) ? g_M[(size_t)n * 128 + f] : 0.f;
            if (f < 32) {
                s[NMS_OFF + f * 65 + e] = v;
            } else {
                int tt = f - 32;
                int uu = tt / 3;
                int ii = tt - uu * 3;
                s[NMV_OFF(ii) + uu * 65 + e] = v;
            }
        }
        // ---- stage node_attrs ----
        for (int q = tid; q < 64 * 16; q += 512) {
            int e = q >> 4, v = q & 15;
            int n = n0 + e;
            s[NNA_OFF + v * 65 + e] = (n < N) ? node_attrs[(size_t)n * 16 + v] : 0.f;
        }

        float accS[4] = {0,0,0,0};
        float accV[3][4] = {{0,0,0,0},{0,0,0,0},{0,0,0,0}};

        for (int u = 0; u < 32; u++) {
            __syncthreads();
            for (int q = tid; q < 1024; q += 512) {
                int v = q >> 6, e = q & 63;
                float nav = s[NNA_OFF + v * 65 + e];
                s[NA0_OFF    + q] = s[NMS_OFF    + u * 65 + e] * nav;
                s[NA1_OFF(0) + q] = s[NMV_OFF(0) + u * 65 + e] * nav;
                s[NA1_OFF(1) + q] = s[NMV_OFF(1) + u * 65 + e] * nav;
                s[NA1_OFF(2) + q] = s[NMV_OFF(2) + u * 65 + e] * nav;
            }
            __syncthreads();

#pragma unroll
            for (int v = 0; v < 16; v++) {
                int k2 = (u << 4) + v;
                float w0 = s[NW_OFF         + k2 * 32 + lane];
                float w1 = s[NW_OFF + 16384 + k2 * 32 + lane];
                int ao = (v << 6) + eb;
                float4 b0  = *(const float4*)&s[NA0_OFF    + ao];
                float4 b10 = *(const float4*)&s[NA1_OFF(0) + ao];
                float4 b11 = *(const float4*)&s[NA1_OFF(1) + ao];
                float4 b12 = *(const float4*)&s[NA1_OFF(2) + ao];

                accS[0] = fmaf(b0.x, w0, accS[0]); accS[1] = fmaf(b0.y, w0, accS[1]);
                accS[2] = fmaf(b0.z, w0, accS[2]); accS[3] = fmaf(b0.w, w0, accS[3]);
                accV[0][0] = fmaf(b10.x, w1, accV[0][0]); accV[0][1] = fmaf(b10.y, w1, accV[0][1]);
                accV[0][2] = fmaf(b10.z, w1, accV[0][2]); accV[0][3] = fmaf(b10.w, w1, accV[0][3]);
                accV[1][0] = fmaf(b11.x, w1, accV[1][0]); accV[1][1] = fmaf(b11.y, w1, accV[1][1]);
                accV[1][2] = fmaf(b11.z, w1, accV[1][2]); accV[1][3] = fmaf(b11.w, w1, accV[1][3]);
                accV[2][0] = fmaf(b12.x, w1, accV[2][0]); accV[2][1] = fmaf(b12.y, w1, accV[2][1]);
                accV[2][2] = fmaf(b12.z, w1, accV[2][2]); accV[2][3] = fmaf(b12.w, w1, accV[2][3]);
            }
        }

        // ---- epilogue: out = M + skip ----
#pragma unroll
        for (int j = 0; j < 4; j++) {
            int e = eb + j;
            int n = n0 + e;
            if (n >= N) continue;
            float* o = out + (size_t)n * 128;
            o[lane]                = s[NMS_OFF    + lane * 65 + e] + accS[j];
            o[32 + lane * 3 + 0]   = s[NMV_OFF(0) + lane * 65 + e] + accV[0][j];
            o[32 + lane * 3 + 1]   = s[NMV_OFF(1) + lane * 65 + e] + accV[1][j];
            o[32 + lane * 3 + 2]   = s[NMV_OFF(2) + lane * 65 + e] + accV[2][j];
        }
    }
}

// ---------------------------------------------------------------------------
// Launch
// ---------------------------------------------------------------------------
extern "C" void kernel_launch(void* const* d_in, const int* in_sizes, int n_in,
                              void* d_out, int out_size)
{
    const float* node_attrs = (const float*)d_in[0];
    const float* node_feats = (const float*)d_in[1];
    const float* edge_attrs = (const float*)d_in[2];
    const float* edge_feats = (const float*)d_in[3];
    const int*   edge_index = (const int*)  d_in[4];
    const float* Wgen       = (const float*)d_in[5];
    const float* L1s        = (const float*)d_in[6];
    const float* L1v        = (const float*)d_in[7];
    const float* WS0        = (const float*)d_in[8];
    const float* WS1        = (const float*)d_in[9];
    const float* L2s        = (const float*)d_in[10];
    const float* L2v        = (const float*)d_in[11];
    float* out = (float*)d_out;

    const int N = in_sizes[0] / ATTRC;        // 10000
    const int E = in_sizes[3] / RADIALC;      // 100000

    cudaFuncSetAttribute(edge_kernel, cudaFuncAttributeMaxDynamicSharedMemorySize, EDGE_SMEM_BYTES);
    cudaFuncSetAttribute(node_kernel, cudaFuncAttributeMaxDynamicSharedMemorySize, NODE_SMEM_BYTES);

    fold_edge_kernel<<<64, 512>>>(Wgen, L1s, L1v);
    fold_node_kernel<<<64, 512>>>(WS0, WS1, L2s, L2v);
    zero_m_kernel<<<(N * 128 + 511) / 512, 512>>>(N * 128);
    edge_kernel<<<148, 512, EDGE_SMEM_BYTES>>>(node_feats, edge_attrs, edge_feats, edge_index, E);
    node_kernel<<<148, 512, NODE_SMEM_BYTES>>>(node_attrs, out, N);
}